// round 1
// baseline (speedup 1.0000x reference)
#include <cuda_runtime.h>
#include <cstdint>

#define BB 8
#define NPTS 2048
#define KNN 32
typedef long long ll;

// ---------------- scratch (device globals; allocation-free) ----------------
static __device__ float g_xT3[BB * NPTS * 3];
static __device__ float g_sqn[BB * NPTS];
static __device__ float g_dist[(ll)BB * NPTS * NPTS];   // also reused as attention matrix
static __device__ int   g_idx[BB * NPTS * KNN];
static __device__ float g_xcT[BB * NPTS * 192];         // concat(f1,f2,f3), point-major
static __device__ float g_h [(ll)BB * 1024 * NPTS];
static __device__ float g_q [(ll)BB * 1024 * NPTS];     // later: h2
static __device__ float g_k [(ll)BB * 1024 * NPTS];     // later: ff out
static __device__ float g_v [(ll)BB * 1024 * NPTS];     // later: h3
static __device__ float g_xr[(ll)BB * 1024 * NPTS];
static __device__ float g_ffb[(ll)BB * 512 * NPTS];

// ---------------- small kernels ----------------
__global__ void transpose_x_kernel(const float* __restrict__ x, float* __restrict__ xt) {
    int i = blockIdx.x * blockDim.x + threadIdx.x;
    if (i >= BB * NPTS) return;
    int b = i / NPTS, n = i % NPTS;
#pragma unroll
    for (int c = 0; c < 3; c++)
        xt[i * 3 + c] = x[(b * 3 + c) * NPTS + n];
}

__global__ void sqnorm_kernel(const float* __restrict__ xt, int rs, int off, int C,
                              float* __restrict__ sq) {
    int i = blockIdx.x * blockDim.x + threadIdx.x;
    if (i >= BB * NPTS) return;
    const float* p = xt + (ll)i * rs + off;
    float s = 0.f;
    for (int c = 0; c < C; c++) { float v = p[c]; s += v * v; }
    sq[i] = s;
}

// ---------------- generic tiled SGEMM ----------------
// C[bz][i,j] = sum_k Aelem(i,k) * Belem(k,j)
// Aelem = TA ? A[k*lda+i] : A[i*lda+k];  Belem = TB ? B[j*ldb+k] : B[k*ldb+j]
// EPI: 0 none, 1 lrelu, 2 bn(p1,bnc)+lrelu, 3 dist: p1[i]+p2[j]-2*acc
template <int TA, int TB, int EPI>
__global__ __launch_bounds__(256, 2)
void gemm_kernel(const float* __restrict__ A, const float* __restrict__ B,
                 float* __restrict__ C, int M, int Nn, int K,
                 int lda, int ldb, int ldc,
                 ll sA, ll sB, ll sC,
                 const float* __restrict__ p1, const float* __restrict__ p2,
                 ll p1s, ll p2s, int bnc) {
    __shared__ float As[16][132];
    __shared__ float Bs[16][132];
    const int tid = threadIdx.x;
    const int tx = tid & 15, ty = tid >> 4;
    const int i0 = blockIdx.y * 128, j0 = blockIdx.x * 128;
    const int bz = blockIdx.z;
    const float* Ab = A + (ll)bz * sA;
    const float* Bb = B + (ll)bz * sB;
    float acc[8][8];
#pragma unroll
    for (int i = 0; i < 8; i++)
#pragma unroll
        for (int j = 0; j < 8; j++) acc[i][j] = 0.f;

    for (int k0 = 0; k0 < K; k0 += 16) {
#pragma unroll
        for (int t = tid; t < 2048; t += 256) {
            int i, kq;
            if (TA) { i = t & 127; kq = t >> 7; } else { kq = t & 15; i = t >> 4; }
            int gi = i0 + i, gk = k0 + kq;
            float v = 0.f;
            if (gi < M && gk < K)
                v = TA ? Ab[(ll)gk * lda + gi] : Ab[(ll)gi * lda + gk];
            As[kq][i] = v;
        }
#pragma unroll
        for (int t = tid; t < 2048; t += 256) {
            int j, kq;
            if (TB) { kq = t & 15; j = t >> 4; } else { j = t & 127; kq = t >> 7; }
            int gj = j0 + j, gk = k0 + kq;
            float v = 0.f;
            if (gj < Nn && gk < K)
                v = TB ? Bb[(ll)gj * ldb + gk] : Bb[(ll)gk * ldb + gj];
            Bs[kq][j] = v;
        }
        __syncthreads();
#pragma unroll
        for (int kq = 0; kq < 16; kq++) {
            float4 a0 = *(const float4*)&As[kq][ty * 8];
            float4 a1 = *(const float4*)&As[kq][ty * 8 + 4];
            float4 b0 = *(const float4*)&Bs[kq][tx * 8];
            float4 b1 = *(const float4*)&Bs[kq][tx * 8 + 4];
            float a[8] = {a0.x, a0.y, a0.z, a0.w, a1.x, a1.y, a1.z, a1.w};
            float b[8] = {b0.x, b0.y, b0.z, b0.w, b1.x, b1.y, b1.z, b1.w};
#pragma unroll
            for (int i = 0; i < 8; i++)
#pragma unroll
                for (int j = 0; j < 8; j++) acc[i][j] += a[i] * b[j];
        }
        __syncthreads();
    }
    float* Cb = C + (ll)bz * sC;
    const float* p1b = p1 ? p1 + (ll)bz * p1s : nullptr;
    const float* p2b = p2 ? p2 + (ll)bz * p2s : nullptr;
#pragma unroll
    for (int ii = 0; ii < 8; ii++) {
        int gi = i0 + ty * 8 + ii;
        if (gi >= M) continue;
        float s = 1.f, t = 0.f, sqi = 0.f;
        if (EPI == 2) {
            float g = p1b[gi], be = p1b[bnc + gi], mm = p1b[2 * bnc + gi], va = p1b[3 * bnc + gi];
            s = g * rsqrtf(va + 1e-5f);
            t = be - mm * s;
        }
        if (EPI == 3) sqi = p1b[gi];
#pragma unroll
        for (int jj = 0; jj < 8; jj++) {
            int gj = j0 + tx * 8 + jj;
            if (gj >= Nn) continue;
            float v = acc[ii][jj];
            if (EPI == 1) v = v >= 0.f ? v : 0.2f * v;
            else if (EPI == 2) { v = v * s + t; v = v >= 0.f ? v : 0.2f * v; }
            else if (EPI == 3) v = sqi + p2b[gj] - 2.f * v;
            Cb[(ll)gi * ldc + gj] = v;
        }
    }
}

// ---------------- top-k (k=32 smallest, ties -> lowest index) ----------------
__global__ __launch_bounds__(256)
void topk_kernel(const float* __restrict__ dist, int* __restrict__ out) {
    __shared__ float sd[NPTS];
    __shared__ float rv[256];
    __shared__ int ri[256];
    const int tid = threadIdx.x;
    const float* row = dist + (ll)blockIdx.x * NPTS;
    for (int t = tid; t < NPTS; t += 256) sd[t] = row[t];
    __syncthreads();
    int* op = out + blockIdx.x * KNN;
    for (int s = 0; s < KNN; s++) {
        float best = 3.4e38f; int bi = NPTS;
        for (int t = tid; t < NPTS; t += 256) {
            float v = sd[t];
            if (v < best) { best = v; bi = t; }
        }
        rv[tid] = best; ri[tid] = bi;
        __syncthreads();
        for (int h = 128; h > 0; h >>= 1) {
            if (tid < h) {
                float ov = rv[tid + h]; int oi = ri[tid + h];
                if (ov < rv[tid] || (ov == rv[tid] && oi < ri[tid])) { rv[tid] = ov; ri[tid] = oi; }
            }
            __syncthreads();
        }
        if (tid == 0) { op[s] = ri[0]; sd[ri[0]] = 3.4e38f; }
        __syncthreads();
    }
}

// ---------------- fused EdgeConv (gather + conv1+bn+lrelu + conv2+bn+lrelu + max_k) ----------------
template <int CIN>
__global__ __launch_bounds__(256)
void edgeconv_kernel(const float* __restrict__ xin, int rsin, int offin,
                     const int* __restrict__ idx,
                     const float* __restrict__ w1, const float* __restrict__ bn1,
                     const float* __restrict__ w2, const float* __restrict__ bn2,
                     float* __restrict__ xout, int rsout, int offout) {
    constexpr int C2 = 2 * CIN;
    extern __shared__ float sm[];
    float* w1s = sm;                       // C2*64 transposed
    float* w2s = w1s + C2 * 64;            // 64*64 transposed
    float* es  = w2s + 4096;               // 32 * C2
    float* h1s = es + 32 * C2;             // 64 * 33 (padded)
    float* red = h1s + 64 * 33;            // 256
    float* ctr = red + 256;                // CIN
    int*   iks = (int*)(ctr + ((CIN + 3) & ~3));  // 32

    const int tid = threadIdx.x;
    const int o = tid & 63, kg = tid >> 6;

    for (int t = tid; t < 64 * C2; t += 256) { int oo = t & 63, c = t >> 6; w1s[t] = w1[oo * C2 + c]; }
    for (int t = tid; t < 4096; t += 256)    { int oo = t & 63, c = t >> 6; w2s[t] = w2[oo * 64 + c]; }
    const float s1 = bn1[o] * rsqrtf(bn1[192 + o] + 1e-5f);
    const float t1 = bn1[64 + o] - bn1[128 + o] * s1;
    const float s2 = bn2[o] * rsqrtf(bn2[192 + o] + 1e-5f);
    const float t2 = bn2[64 + o] - bn2[128 + o] * s2;
    __syncthreads();

    for (int p = blockIdx.x; p < BB * NPTS; p += gridDim.x) {
        const int b = p >> 11;
        if (tid < CIN) ctr[tid] = xin[(ll)p * rsin + offin + tid];
        if (tid < KNN) iks[tid] = idx[p * KNN + tid];
        __syncthreads();
        for (int t = tid; t < KNN * CIN; t += 256) {
            int kq = t / CIN, c = t - kq * CIN;
            int m = iks[kq];
            float v = xin[(ll)(b * NPTS + m) * rsin + offin + c];
            es[kq * C2 + c] = v - ctr[c];
            es[kq * C2 + CIN + c] = ctr[c];
        }
        __syncthreads();
        float acc[8];
#pragma unroll
        for (int j = 0; j < 8; j++) acc[j] = 0.f;
        for (int c = 0; c < C2; c++) {
            float w = w1s[c * 64 + o];
#pragma unroll
            for (int j = 0; j < 8; j++) acc[j] += w * es[(kg * 8 + j) * C2 + c];
        }
#pragma unroll
        for (int j = 0; j < 8; j++) {
            float v = acc[j] * s1 + t1;
            v = v >= 0.f ? v : 0.2f * v;
            h1s[o * 33 + kg * 8 + j] = v;
            acc[j] = 0.f;
        }
        __syncthreads();
        for (int c = 0; c < 64; c++) {
            float w = w2s[c * 64 + o];
#pragma unroll
            for (int j = 0; j < 8; j++) acc[j] += w * h1s[c * 33 + kg * 8 + j];
        }
        float mx = -3.4e38f;
#pragma unroll
        for (int j = 0; j < 8; j++) {
            float v = acc[j] * s2 + t2;
            v = v >= 0.f ? v : 0.2f * v;
            mx = fmaxf(mx, v);
        }
        red[kg * 64 + o] = mx;
        __syncthreads();
        if (kg == 0) {
            float m = fmaxf(fmaxf(red[o], red[64 + o]), fmaxf(red[128 + o], red[192 + o]));
            xout[(ll)p * rsout + offout + o] = m;
        }
        __syncthreads();
    }
}

// ---------------- softmax over last dim (with 1/32 scale folded in) ----------------
__global__ __launch_bounds__(256)
void softmax_kernel(float* __restrict__ att) {
    __shared__ float sd[NPTS];
    __shared__ float red[256];
    const int tid = threadIdx.x;
    float* p = att + (ll)blockIdx.x * NPTS;
    float mx = -3.4e38f;
    for (int t = tid; t < NPTS; t += 256) {
        float v = p[t] * 0.03125f;
        sd[t] = v;
        mx = fmaxf(mx, v);
    }
    red[tid] = mx;
    __syncthreads();
    for (int h = 128; h > 0; h >>= 1) {
        if (tid < h) red[tid] = fmaxf(red[tid], red[tid + h]);
        __syncthreads();
    }
    mx = red[0];
    __syncthreads();
    float sum = 0.f;
    for (int t = tid; t < NPTS; t += 256) {
        float e = expf(sd[t] - mx);
        sd[t] = e;
        sum += e;
    }
    red[tid] = sum;
    __syncthreads();
    for (int h = 128; h > 0; h >>= 1) {
        if (tid < h) red[tid] += red[tid + h];
        __syncthreads();
    }
    float inv = 1.f / red[0];
    __syncthreads();
    for (int t = tid; t < NPTS; t += 256) p[t] = sd[t] * inv;
}

// ---------------- residual add + BN ----------------
__global__ void addbn_kernel(const float* __restrict__ a, const float* __restrict__ r,
                             const float* __restrict__ bn, float* __restrict__ out,
                             int C, ll total) {
    ll i = (ll)blockIdx.x * blockDim.x + threadIdx.x;
    if (i >= total) return;
    int c = (int)((i / NPTS) % C);
    float g = bn[c], be = bn[C + c], m = bn[2 * C + c], va = bn[3 * C + c];
    float s = g * rsqrtf(va + 1e-5f);
    out[i] = (a[i] + r[i]) * s + (be - m * s);
}

// ---------------- launcher ----------------
extern "C" void kernel_launch(void* const* d_in, const int* in_sizes, int n_in,
                              void* d_out, int out_size) {
    const float* x       = (const float*)d_in[0];
    const float* ec1_w1  = (const float*)d_in[1];
    const float* ec1_bn1 = (const float*)d_in[2];
    const float* ec1_w2  = (const float*)d_in[3];
    const float* ec1_bn2 = (const float*)d_in[4];
    const float* ec2_w1  = (const float*)d_in[5];
    const float* ec2_bn1 = (const float*)d_in[6];
    const float* ec2_w2  = (const float*)d_in[7];
    const float* ec2_bn2 = (const float*)d_in[8];
    const float* ec3_w1  = (const float*)d_in[9];
    const float* ec3_bn1 = (const float*)d_in[10];
    const float* ec3_w2  = (const float*)d_in[11];
    const float* ec3_bn2 = (const float*)d_in[12];
    const float* emb_w   = (const float*)d_in[13];
    const float* q_w     = (const float*)d_in[14];
    const float* k_w     = (const float*)d_in[15];
    const float* v_w     = (const float*)d_in[16];
    const float* att_bn1 = (const float*)d_in[17];
    const float* ff_w1   = (const float*)d_in[18];
    const float* ff_w2   = (const float*)d_in[19];
    const float* att_bn2 = (const float*)d_in[20];
    const float* cb_w    = (const float*)d_in[21];
    const float* cb_bn   = (const float*)d_in[22];
    float* out = (float*)d_out;

    float *xT3, *sqn, *dist, *xcT, *h, *q, *kk, *v, *xr, *ffb;
    int* idxp;
    cudaGetSymbolAddress((void**)&xT3, g_xT3);
    cudaGetSymbolAddress((void**)&sqn, g_sqn);
    cudaGetSymbolAddress((void**)&dist, g_dist);
    cudaGetSymbolAddress((void**)&idxp, g_idx);
    cudaGetSymbolAddress((void**)&xcT, g_xcT);
    cudaGetSymbolAddress((void**)&h, g_h);
    cudaGetSymbolAddress((void**)&q, g_q);
    cudaGetSymbolAddress((void**)&kk, g_k);
    cudaGetSymbolAddress((void**)&v, g_v);
    cudaGetSymbolAddress((void**)&xr, g_xr);
    cudaGetSymbolAddress((void**)&ffb, g_ffb);

    const size_t sm3  = (size_t)(6 * 64 + 4096 + 32 * 6 + 64 * 33 + 256 + 4 + 32) * 4;
    const size_t sm64 = (size_t)(128 * 64 + 4096 + 32 * 128 + 64 * 33 + 256 + 64 + 32) * 4;
    cudaFuncSetAttribute((const void*)edgeconv_kernel<64>,
                         cudaFuncAttributeMaxDynamicSharedMemorySize, (int)sm64);

    const int npts = BB * NPTS;
    const ll CH = (ll)1024 * NPTS;
    const ll AT = (ll)NPTS * NPTS;
    const ll total = (ll)BB * 1024 * NPTS;

    transpose_x_kernel<<<(npts + 255) / 256, 256>>>(x, xT3);

    // ---- EdgeConv 1 (C=3) ----
    sqnorm_kernel<<<(npts + 255) / 256, 256>>>(xT3, 3, 0, 3, sqn);
    dim3 gd(NPTS / 128, NPTS / 128, BB);
    gemm_kernel<0, 1, 3><<<gd, 256>>>(xT3, xT3, dist, NPTS, NPTS, 3, 3, 3, NPTS,
                                      (ll)NPTS * 3, (ll)NPTS * 3, AT,
                                      sqn, sqn, NPTS, NPTS, 0);
    topk_kernel<<<npts, 256>>>(dist, idxp);
    edgeconv_kernel<3><<<1024, 256, sm3>>>(xT3, 3, 0, idxp, ec1_w1, ec1_bn1, ec1_w2, ec1_bn2,
                                           xcT, 192, 0);

    // ---- EdgeConv 2 (C=64, input f1 = xcT cols [0,64)) ----
    sqnorm_kernel<<<(npts + 255) / 256, 256>>>(xcT, 192, 0, 64, sqn);
    gemm_kernel<0, 1, 3><<<gd, 256>>>(xcT, xcT, dist, NPTS, NPTS, 64, 192, 192, NPTS,
                                      (ll)NPTS * 192, (ll)NPTS * 192, AT,
                                      sqn, sqn, NPTS, NPTS, 0);
    topk_kernel<<<npts, 256>>>(dist, idxp);
    edgeconv_kernel<64><<<1024, 256, sm64>>>(xcT, 192, 0, idxp, ec2_w1, ec2_bn1, ec2_w2, ec2_bn2,
                                             xcT, 192, 64);

    // ---- EdgeConv 3 (C=64, input f2 = xcT cols [64,128)) ----
    sqnorm_kernel<<<(npts + 255) / 256, 256>>>(xcT, 192, 64, 64, sqn);
    gemm_kernel<0, 1, 3><<<gd, 256>>>(xcT + 64, xcT + 64, dist, NPTS, NPTS, 64, 192, 192, NPTS,
                                      (ll)NPTS * 192, (ll)NPTS * 192, AT,
                                      sqn, sqn, NPTS, NPTS, 0);
    topk_kernel<<<npts, 256>>>(dist, idxp);
    edgeconv_kernel<64><<<1024, 256, sm64>>>(xcT, 192, 64, idxp, ec3_w1, ec3_bn1, ec3_w2, ec3_bn2,
                                             xcT, 192, 128);

    // ---- embedding + attention + FF + classifier ----
    dim3 ge(NPTS / 128, 1024 / 128, BB);
    gemm_kernel<0, 1, 0><<<ge, 256>>>(emb_w, xcT, h, 1024, NPTS, 192, 192, 192, NPTS,
                                      0, (ll)NPTS * 192, CH, nullptr, nullptr, 0, 0, 0);
    gemm_kernel<0, 0, 0><<<ge, 256>>>(q_w, h, q, 1024, NPTS, 1024, 1024, NPTS, NPTS,
                                      0, CH, CH, nullptr, nullptr, 0, 0, 0);
    gemm_kernel<0, 0, 0><<<ge, 256>>>(k_w, h, kk, 1024, NPTS, 1024, 1024, NPTS, NPTS,
                                      0, CH, CH, nullptr, nullptr, 0, 0, 0);
    gemm_kernel<0, 0, 0><<<ge, 256>>>(v_w, h, v, 1024, NPTS, 1024, 1024, NPTS, NPTS,
                                      0, CH, CH, nullptr, nullptr, 0, 0, 0);
    dim3 ga(NPTS / 128, NPTS / 128, BB);
    gemm_kernel<1, 0, 0><<<ga, 256>>>(q, kk, dist, NPTS, NPTS, 1024, NPTS, NPTS, NPTS,
                                      CH, CH, AT, nullptr, nullptr, 0, 0, 0);
    softmax_kernel<<<npts, 256>>>(dist);
    gemm_kernel<0, 1, 0><<<ge, 256>>>(v, dist, xr, 1024, NPTS, NPTS, NPTS, NPTS, NPTS,
                                      CH, AT, CH, nullptr, nullptr, 0, 0, 0);
    addbn_kernel<<<(int)((total + 255) / 256), 256>>>(h, xr, att_bn1, q /*h2*/, 1024, total);
    dim3 gf(NPTS / 128, 512 / 128, BB);
    gemm_kernel<0, 0, 1><<<gf, 256>>>(ff_w1, q, ffb, 512, NPTS, 1024, 1024, NPTS, NPTS,
                                      0, CH, (ll)512 * NPTS, nullptr, nullptr, 0, 0, 0);
    gemm_kernel<0, 0, 0><<<ge, 256>>>(ff_w2, ffb, kk /*ff out*/, 1024, NPTS, 512, 512, NPTS, NPTS,
                                      0, (ll)512 * NPTS, CH, nullptr, nullptr, 0, 0, 0);
    addbn_kernel<<<(int)((total + 255) / 256), 256>>>(q, kk, att_bn2, v /*h3*/, 1024, total);
    gemm_kernel<0, 0, 2><<<ge, 256>>>(cb_w, v, out, 1024, NPTS, 1024, 1024, NPTS, NPTS,
                                      0, CH, CH, cb_bn, nullptr, 0, 0, 1024);
}